// round 16
// baseline (speedup 1.0000x reference)
#include <cuda_runtime.h>
#include <cstdint>

#define SEQ   4096
#define BATCH 64
#define INP   64
#define HID   256
#define G3    768
#define BG    16          // batch columns (4 batches each)
#define HG    8           // hidden groups (32 units each) = warps/CTA
#define NCTA  (BG*HG)     // 128 scan CTAs, occupancy 1

// Scratch (static device allocations are the sanctioned workaround)
__device__ float d_xg[(size_t)SEQ * G3 * BATCH];             // [s][g][b]
__device__ unsigned long long d_hmail[2 * BG * HG * 32 * 4]; // [par][bg][p][j][b]
__device__ float d_fcp[(size_t)NCTA * SEQ * 4];              // [bg*8+hg][t][b4]

__device__ __forceinline__ void fma2(unsigned long long& acc,
                                     unsigned long long a,
                                     unsigned long long b) {
    asm("fma.rn.f32x2 %0, %1, %2, %0;" : "+l"(acc) : "l"(a), "l"(b));
}
__device__ __forceinline__ unsigned long long pk(float a, float b) {
    unsigned long long r;
    asm("mov.b64 %0, {%1, %2};" : "=l"(r) : "f"(a), "f"(b));
    return r;
}
__device__ __forceinline__ float2 unpk(unsigned long long v) {
    float lo, hi;
    asm("mov.b64 {%0, %1}, %2;" : "=f"(lo), "=f"(hi) : "l"(v));
    return make_float2(lo, hi);
}
__device__ __forceinline__ float tanh_fast(float x) {
    float r;
    asm("tanh.approx.f32 %0, %1;" : "=f"(r) : "f"(x));
    return r;
}
__device__ __forceinline__ float sigmoid_fast(float x) {
    return fmaf(tanh_fast(0.5f * x), 0.5f, 0.5f);
}
#define LDV2(lo, hi, addr) \
    asm volatile("ld.volatile.global.v2.u64 {%0,%1}, [%2];" \
                 : "=l"(lo), "=l"(hi) : "l"(addr))

// ---------------------------------------------------------------------------
// Kernel A: xg[s][g][b] = sum_i x[s][b][i] * w_ih[g][i] + b_ih[g]
// ---------------------------------------------------------------------------
__global__ void __launch_bounds__(256) xg_kernel(const float* __restrict__ x,
                                                 const float* __restrict__ w_ih,
                                                 const float* __restrict__ b_ih) {
    __shared__ float xs[INP][BATCH + 1];
    __shared__ float ws[64][INP];
    const int s   = blockIdx.x;
    const int g0  = blockIdx.y * 64;
    const int tid = threadIdx.x;

    const float* xsrc = x + (size_t)s * BATCH * INP;
    for (int idx = tid; idx < BATCH * INP; idx += 256) {
        int b = idx >> 6, i = idx & 63;
        xs[i][b] = xsrc[idx];
    }
    const float* wsrc = w_ih + (size_t)g0 * INP;
    for (int idx = tid; idx < 64 * INP; idx += 256)
        ws[idx >> 6][idx & 63] = wsrc[idx];
    __syncthreads();

    const int b  = tid & 63;
    const int gg = tid >> 6;
    float xr[INP];
#pragma unroll
    for (int i = 0; i < INP; i++) xr[i] = xs[i][b];

    float acc[16];
#pragma unroll
    for (int u = 0; u < 16; u++) acc[u] = 0.0f;
    const int gb = gg * 16;
#pragma unroll
    for (int i4 = 0; i4 < INP / 4; i4++) {
#pragma unroll
        for (int u = 0; u < 16; u++) {
            float4 w4 = *(const float4*)&ws[gb + u][i4 * 4];
            acc[u] += w4.x * xr[i4 * 4 + 0];
            acc[u] += w4.y * xr[i4 * 4 + 1];
            acc[u] += w4.z * xr[i4 * 4 + 2];
            acc[u] += w4.w * xr[i4 * 4 + 3];
        }
    }
    float* dst = d_xg + ((size_t)s * G3 + g0) * BATCH;
#pragma unroll
    for (int u = 0; u < 16; u++) {
        int gl = gb + u;
        __stcs(&dst[(size_t)gl * BATCH + b], acc[u] + b_ih[g0 + gl]);
    }
}

// ---------------------------------------------------------------------------
// Kernel B: persistent GRU scan, warp-per-producer ready-order consumption,
// tanh.approx activations (R15 base). SINGLE CHANGE: software-pipelined
// mail poll — two volatile load-sets ping-ponged so each epoch check
// consumes a load issued one iteration earlier (check period ~RT/2), and
// per-lane exit (no ballot in the loop; lanes meet at the __syncwarp).
// ---------------------------------------------------------------------------
__global__ void __launch_bounds__(256, 1) scan_kernel(const float* __restrict__ w_hh,
                                                      const float* __restrict__ b_hh,
                                                      const float* __restrict__ fc_w) {
    __shared__ float hsm[HG][4][32];       // [warp][b_local][k_local]
    __shared__ float red[HG][3][128];      // [warp][gate][j*4+b]
    __shared__ float fcred[4][32];         // [b_local][j]

    const int c    = blockIdx.x;
    const int bg   = c & (BG - 1);
    const int hg   = c >> 4;
    const int tid  = threadIdx.x;
    const int w    = tid >> 5;             // warp = producer index = k strip
    const int lane = tid & 31;

    // Weights: unit u = hg*32+lane, k in [w*32, w*32+32), k-paired as float2
    unsigned long long w2[3][16];
#pragma unroll
    for (int g = 0; g < 3; g++)
#pragma unroll
        for (int q = 0; q < 8; q++) {
            const float4 v = *(const float4*)&w_hh[
                ((size_t)(g * HID + hg * 32 + lane)) * HID + w * 32 + q * 4];
            w2[g][q * 2 + 0] = pk(v.x, v.y);
            w2[g][q * 2 + 1] = pk(v.z, v.w);
        }

    // Pointwise mapping (tid < 128): unit pj, batch pb
    const int pj = tid >> 2;
    const int pb = tid & 3;
    const int u  = hg * 32 + pj;
    const float bh_r = b_hh[u];
    const float bh_z = b_hh[HID + u];
    const float bh_n = b_hh[2 * HID + u];
    const float fw   = fc_w[u];

    float h_prev = 0.0f;
    __syncthreads();

    for (int t = 0; t < SEQ; t++) {
        // Prefetch input-side gates (overlaps poll + MAC)
        float xrv = 0.f, xzv = 0.f, xnv = 0.f;
        if (tid < 128) {
            const size_t base = ((size_t)t * G3 + u) * BATCH + (bg * 4 + pb);
            xrv = __ldcs(&d_xg[base]);
            xzv = __ldcs(&d_xg[base + (size_t)HID * BATCH]);
            xnv = __ldcs(&d_xg[base + (size_t)2 * HID * BATCH]);
        }

        unsigned long long acc[3][4];      // [gate][b], f32x2 over (k0,k1)
#pragma unroll
        for (int g = 0; g < 3; g++)
#pragma unroll
            for (int b = 0; b < 4; b++) acc[g][b] = 0ull;

        if (t > 0) {
            // Pipelined per-lane poll of producer w's mail (epoch t)
            const unsigned long long tt = (unsigned long long)t;
            const unsigned long long* mp = &d_hmail[
                ((size_t)(((t - 1) & 1) * BG + bg) * HG + w) * 128 + lane * 4];
            unsigned long long a0, a1, a2, a3, b0, b1, b2, b3;
            LDV2(a0, a1, mp); LDV2(a2, a3, mp + 2);      // set A in flight
            for (;;) {
                LDV2(b0, b1, mp); LDV2(b2, b3, mp + 2);  // set B in flight
                if (((a0 >> 32) == tt) & ((a1 >> 32) == tt) &
                    ((a2 >> 32) == tt) & ((a3 >> 32) == tt))
                    break;                               // consume A
                LDV2(a0, a1, mp); LDV2(a2, a3, mp + 2);  // set A in flight
                if (((b0 >> 32) == tt) & ((b1 >> 32) == tt) &
                    ((b2 >> 32) == tt) & ((b3 >> 32) == tt)) {
                    a0 = b0; a1 = b1; a2 = b2; a3 = b3;  // consume B
                    break;
                }
            }
            hsm[w][0][lane] = __uint_as_float((unsigned)a0);
            hsm[w][1][lane] = __uint_as_float((unsigned)a1);
            hsm[w][2][lane] = __uint_as_float((unsigned)a2);
            hsm[w][3][lane] = __uint_as_float((unsigned)a3);
            __syncwarp();                  // warp-local staging only

            // Strip MAC: 192 fma2, hsm loads broadcast (same addr all lanes)
#pragma unroll
            for (int b = 0; b < 4; b++) {
#pragma unroll
                for (int q = 0; q < 8; q++) {
                    const ulonglong2 hh = *(const ulonglong2*)&hsm[w][b][q * 4];
#pragma unroll
                    for (int g = 0; g < 3; g++) {
                        fma2(acc[g][b], w2[g][q * 2 + 0], hh.x);
                        fma2(acc[g][b], w2[g][q * 2 + 1], hh.y);
                    }
                }
            }
        }

        // Store per-warp partials: lane = unit, pack 4 batches per gate
#pragma unroll
        for (int g = 0; g < 3; g++) {
            const float2 a0 = unpk(acc[g][0]);
            const float2 a1 = unpk(acc[g][1]);
            const float2 a2 = unpk(acc[g][2]);
            const float2 a3 = unpk(acc[g][3]);
            float4 v = make_float4(a0.x + a0.y, a1.x + a1.y,
                                   a2.x + a2.y, a3.x + a3.y);
            *(float4*)&red[w][g][lane * 4] = v;
        }
        __syncthreads();                   // all warps' partials visible

        if (tid < 128) {
            float sr = 0.f, sz = 0.f, sn = 0.f;
            const int o = pj * 4 + pb;
#pragma unroll
            for (int ww = 0; ww < HG; ww++) {
                sr += red[ww][0][o];
                sz += red[ww][1][o];
                sn += red[ww][2][o];
            }
            // torch GRU: n = tanh(xn + r*(hn + bhh_n)), HW-approx activations
            const float rg_ = sigmoid_fast(xrv + sr + bh_r);
            const float zg_ = sigmoid_fast(xzv + sz + bh_z);
            const float ng_ = tanh_fast(xnv + rg_ * (sn + bh_n));
            const float hnew = fmaf(zg_, h_prev - ng_, ng_);
            h_prev = hnew;
            // Publish mail immediately: epoch t+1 | value, parity t&1
            const unsigned long long mail =
                ((unsigned long long)(t + 1) << 32) |
                (unsigned long long)__float_as_uint(hnew);
            unsigned long long* maddr = &d_hmail[
                ((size_t)((t & 1) * BG + bg) * HG + hg) * 128 + pj * 4 + pb];
            asm volatile("st.relaxed.gpu.global.u64 [%0], %1;"
                         :: "l"(maddr), "l"(mail) : "memory");
            fcred[pb][pj] = fw * hnew;
        }
        __syncthreads();                   // fcred ready; red reusable

        if (tid < 4) {                     // fc partial (off critical path)
            float fs = 0.0f;
#pragma unroll
            for (int j = 0; j < 32; j++) fs += fcred[tid][j];
            d_fcp[((size_t)(bg * HG + hg) * SEQ + t) * 4 + tid] = fs;
        }
    }
}

// ---------------------------------------------------------------------------
// Kernel C: out[s][b] = fc_b + sum_hg fcp; re-zeroes the mailbox for replay.
// ---------------------------------------------------------------------------
__global__ void __launch_bounds__(512) final_kernel(const float* __restrict__ fc_b,
                                                    float* __restrict__ out) {
    const int idx = blockIdx.x * 512 + threadIdx.x;
    if (idx < 2 * BG * HG * 32 * 4)                  // 32768 u64 mail words
        d_hmail[idx] = 0ull;
    if (idx >= SEQ * BATCH) return;
    const int s  = idx >> 6;
    const int b6 = idx & 63;
    const int bg = b6 >> 2;
    const int bl = b6 & 3;
    float sum = fc_b[0];
#pragma unroll
    for (int hg = 0; hg < HG; hg++)
        sum += d_fcp[((size_t)(bg * HG + hg) * SEQ + s) * 4 + bl];
    out[idx] = sum;
}

extern "C" void kernel_launch(void* const* d_in, const int* in_sizes, int n_in,
                              void* d_out, int out_size) {
    const float* x    = (const float*)d_in[0];
    const float* w_ih = (const float*)d_in[1];
    const float* w_hh = (const float*)d_in[2];
    const float* b_ih = (const float*)d_in[3];
    const float* b_hh = (const float*)d_in[4];
    const float* fc_w = (const float*)d_in[5];
    const float* fc_b = (const float*)d_in[6];
    float* out = (float*)d_out;

    dim3 ga(SEQ, G3 / 64);
    xg_kernel<<<ga, 256>>>(x, w_ih, b_ih);                 // input projections
    scan_kernel<<<NCTA, 256>>>(w_hh, b_hh, fc_w);          // ready-order scan
    final_kernel<<<(SEQ * BATCH + 511) / 512, 512>>>(fc_b, out);
}

// round 17
// speedup vs baseline: 1.0622x; 1.0622x over previous
#include <cuda_runtime.h>
#include <cstdint>

#define SEQ   4096
#define BATCH 64
#define INP   64
#define HID   256
#define G3    768
#define BG    16          // batch columns (4 batches each)
#define HG    8           // hidden groups (32 units each) = warps/CTA
#define NCTA  (BG*HG)     // 128 scan CTAs, occupancy 1

// Scratch (static device allocations are the sanctioned workaround)
__device__ float d_xg[(size_t)SEQ * G3 * BATCH];             // [s][g][b]
__device__ unsigned long long d_hmail[2 * BG * HG * 32 * 4]; // [par][bg][p][j][b]
__device__ float d_fcp[(size_t)NCTA * SEQ * 4];              // [bg*8+hg][t][b4]

__device__ __forceinline__ void fma2(unsigned long long& acc,
                                     unsigned long long a,
                                     unsigned long long b) {
    asm("fma.rn.f32x2 %0, %1, %2, %0;" : "+l"(acc) : "l"(a), "l"(b));
}
__device__ __forceinline__ void add2(unsigned long long& acc,
                                     unsigned long long a) {
    asm("add.rn.f32x2 %0, %0, %1;" : "+l"(acc) : "l"(a));
}
__device__ __forceinline__ unsigned long long pk(float a, float b) {
    unsigned long long r;
    asm("mov.b64 %0, {%1, %2};" : "=l"(r) : "f"(a), "f"(b));
    return r;
}
__device__ __forceinline__ float2 unpk(unsigned long long v) {
    float lo, hi;
    asm("mov.b64 {%0, %1}, %2;" : "=f"(lo), "=f"(hi) : "l"(v));
    return make_float2(lo, hi);
}
__device__ __forceinline__ float tanh_fast(float x) {
    float r;
    asm("tanh.approx.f32 %0, %1;" : "=f"(r) : "f"(x));
    return r;
}
__device__ __forceinline__ float sigmoid_fast(float x) {
    return fmaf(tanh_fast(0.5f * x), 0.5f, 0.5f);
}

// ---------------------------------------------------------------------------
// Kernel A: xg[s][g][b] = sum_i x[s][b][i] * w_ih[g][i] + b_ih[g]
// ---------------------------------------------------------------------------
__global__ void __launch_bounds__(256) xg_kernel(const float* __restrict__ x,
                                                 const float* __restrict__ w_ih,
                                                 const float* __restrict__ b_ih) {
    __shared__ float xs[INP][BATCH + 1];
    __shared__ float ws[64][INP];
    const int s   = blockIdx.x;
    const int g0  = blockIdx.y * 64;
    const int tid = threadIdx.x;

    const float* xsrc = x + (size_t)s * BATCH * INP;
    for (int idx = tid; idx < BATCH * INP; idx += 256) {
        int b = idx >> 6, i = idx & 63;
        xs[i][b] = xsrc[idx];
    }
    const float* wsrc = w_ih + (size_t)g0 * INP;
    for (int idx = tid; idx < 64 * INP; idx += 256)
        ws[idx >> 6][idx & 63] = wsrc[idx];
    __syncthreads();

    const int b  = tid & 63;
    const int gg = tid >> 6;
    float xr[INP];
#pragma unroll
    for (int i = 0; i < INP; i++) xr[i] = xs[i][b];

    float acc[16];
#pragma unroll
    for (int u = 0; u < 16; u++) acc[u] = 0.0f;
    const int gb = gg * 16;
#pragma unroll
    for (int i4 = 0; i4 < INP / 4; i4++) {
#pragma unroll
        for (int u = 0; u < 16; u++) {
            float4 w4 = *(const float4*)&ws[gb + u][i4 * 4];
            acc[u] += w4.x * xr[i4 * 4 + 0];
            acc[u] += w4.y * xr[i4 * 4 + 1];
            acc[u] += w4.z * xr[i4 * 4 + 2];
            acc[u] += w4.w * xr[i4 * 4 + 3];
        }
    }
    float* dst = d_xg + ((size_t)s * G3 + g0) * BATCH;
#pragma unroll
    for (int u = 0; u < 16; u++) {
        int gl = gb + u;
        __stcs(&dst[(size_t)gl * BATCH + b], acc[u] + b_ih[g0 + gl]);
    }
}

// ---------------------------------------------------------------------------
// Kernel B: persistent GRU scan, warp-per-producer ready-order consumption,
// tanh.approx activations (R15 base = 6.10ms). SINGLE CHANGE: (r,z) gate
// partials packed as f32x2 u64 — combine is 8 LDS.64 + 7 add.f32x2 (r,z
// jointly) + 8 LDS.32 + 7 FADD (n), down from 24 LDS + 21 FADD.
// ---------------------------------------------------------------------------
__global__ void __launch_bounds__(256, 1) scan_kernel(const float* __restrict__ w_hh,
                                                      const float* __restrict__ b_hh,
                                                      const float* __restrict__ fc_w) {
    __shared__ float hsm[HG][4][32];                   // [warp][b_local][k_local]
    __shared__ __align__(16) unsigned long long red_rz[HG][128]; // (r,z) per [w][j*4+b]
    __shared__ float red_n[HG][128];                   // n partials [w][j*4+b]
    __shared__ float fcred[4][32];                     // [b_local][j]

    const int c    = blockIdx.x;
    const int bg   = c & (BG - 1);
    const int hg   = c >> 4;
    const int tid  = threadIdx.x;
    const int w    = tid >> 5;             // warp = producer index = k strip
    const int lane = tid & 31;

    // Weights: unit u = hg*32+lane, k in [w*32, w*32+32), k-paired as float2
    unsigned long long w2[3][16];
#pragma unroll
    for (int g = 0; g < 3; g++)
#pragma unroll
        for (int q = 0; q < 8; q++) {
            const float4 v = *(const float4*)&w_hh[
                ((size_t)(g * HID + hg * 32 + lane)) * HID + w * 32 + q * 4];
            w2[g][q * 2 + 0] = pk(v.x, v.y);
            w2[g][q * 2 + 1] = pk(v.z, v.w);
        }

    // Pointwise mapping (tid < 128): unit pj, batch pb
    const int pj = tid >> 2;
    const int pb = tid & 3;
    const int u  = hg * 32 + pj;
    const float bh_r = b_hh[u];
    const float bh_z = b_hh[HID + u];
    const float bh_n = b_hh[2 * HID + u];
    const float fw   = fc_w[u];

    float h_prev = 0.0f;
    __syncthreads();

    for (int t = 0; t < SEQ; t++) {
        // Prefetch input-side gates (overlaps poll + MAC)
        float xrv = 0.f, xzv = 0.f, xnv = 0.f;
        if (tid < 128) {
            const size_t base = ((size_t)t * G3 + u) * BATCH + (bg * 4 + pb);
            xrv = __ldcs(&d_xg[base]);
            xzv = __ldcs(&d_xg[base + (size_t)HID * BATCH]);
            xnv = __ldcs(&d_xg[base + (size_t)2 * HID * BATCH]);
        }

        unsigned long long acc[3][4];      // [gate][b], f32x2 over (k0,k1)
#pragma unroll
        for (int g = 0; g < 3; g++)
#pragma unroll
            for (int b = 0; b < 4; b++) acc[g][b] = 0ull;

        if (t > 0) {
            // Warp w polls ONLY producer w's mail (epoch t, parity (t-1)&1)
            const unsigned long long tt = (unsigned long long)t;
            const unsigned long long* mp = &d_hmail[
                ((size_t)(((t - 1) & 1) * BG + bg) * HG + w) * 128 + lane * 4];
            unsigned long long m0, m1, m2, m3;
            bool ok;
            do {
                asm volatile("ld.volatile.global.v2.u64 {%0,%1}, [%2];"
                             : "=l"(m0), "=l"(m1) : "l"(mp));
                asm volatile("ld.volatile.global.v2.u64 {%0,%1}, [%2];"
                             : "=l"(m2), "=l"(m3) : "l"(mp + 2));
                ok = __all_sync(0xFFFFFFFFu,
                                ((m0 >> 32) == tt) & ((m1 >> 32) == tt) &
                                ((m2 >> 32) == tt) & ((m3 >> 32) == tt));
            } while (!ok);
            hsm[w][0][lane] = __uint_as_float((unsigned)m0);
            hsm[w][1][lane] = __uint_as_float((unsigned)m1);
            hsm[w][2][lane] = __uint_as_float((unsigned)m2);
            hsm[w][3][lane] = __uint_as_float((unsigned)m3);
            __syncwarp();                  // warp-local staging only

            // Strip MAC: 192 fma2, hsm loads broadcast (same addr all lanes)
#pragma unroll
            for (int b = 0; b < 4; b++) {
#pragma unroll
                for (int q = 0; q < 8; q++) {
                    const ulonglong2 hh = *(const ulonglong2*)&hsm[w][b][q * 4];
#pragma unroll
                    for (int g = 0; g < 3; g++) {
                        fma2(acc[g][b], w2[g][q * 2 + 0], hh.x);
                        fma2(acc[g][b], w2[g][q * 2 + 1], hh.y);
                    }
                }
            }
        }

        // Per-warp partials: (r,z) packed as f32x2 u64; n as float
#pragma unroll
        for (int b = 0; b < 4; b += 2) {
            const float2 r0 = unpk(acc[0][b]);
            const float2 z0 = unpk(acc[1][b]);
            const float2 r1 = unpk(acc[0][b + 1]);
            const float2 z1 = unpk(acc[1][b + 1]);
            ulonglong2 vv;
            vv.x = pk(r0.x + r0.y, z0.x + z0.y);
            vv.y = pk(r1.x + r1.y, z1.x + z1.y);
            *(ulonglong2*)&red_rz[w][lane * 4 + b] = vv;
        }
        {
            const float2 n0 = unpk(acc[2][0]);
            const float2 n1 = unpk(acc[2][1]);
            const float2 n2 = unpk(acc[2][2]);
            const float2 n3 = unpk(acc[2][3]);
            float4 v = make_float4(n0.x + n0.y, n1.x + n1.y,
                                   n2.x + n2.y, n3.x + n3.y);
            *(float4*)&red_n[w][lane * 4] = v;
        }
        __syncthreads();                   // all warps' partials visible

        if (tid < 128) {
            const int o = pj * 4 + pb;
            unsigned long long srz = red_rz[0][o];
            float sn = red_n[0][o];
#pragma unroll
            for (int ww = 1; ww < HG; ww++) {
                add2(srz, red_rz[ww][o]);
                sn += red_n[ww][o];
            }
            const float2 rz = unpk(srz);
            // torch GRU: n = tanh(xn + r*(hn + bhh_n)), HW-approx activations
            const float rg_ = sigmoid_fast(xrv + rz.x + bh_r);
            const float zg_ = sigmoid_fast(xzv + rz.y + bh_z);
            const float ng_ = tanh_fast(xnv + rg_ * (sn + bh_n));
            const float hnew = fmaf(zg_, h_prev - ng_, ng_);
            h_prev = hnew;
            // Publish mail immediately: epoch t+1 | value, parity t&1
            const unsigned long long mail =
                ((unsigned long long)(t + 1) << 32) |
                (unsigned long long)__float_as_uint(hnew);
            unsigned long long* maddr = &d_hmail[
                ((size_t)((t & 1) * BG + bg) * HG + hg) * 128 + pj * 4 + pb];
            asm volatile("st.relaxed.gpu.global.u64 [%0], %1;"
                         :: "l"(maddr), "l"(mail) : "memory");
            fcred[pb][pj] = fw * hnew;
        }
        __syncthreads();                   // fcred ready; red reusable

        if (tid < 4) {                     // fc partial (off critical path)
            float fs = 0.0f;
#pragma unroll
            for (int j = 0; j < 32; j++) fs += fcred[tid][j];
            d_fcp[((size_t)(bg * HG + hg) * SEQ + t) * 4 + tid] = fs;
        }
    }
}

// ---------------------------------------------------------------------------
// Kernel C: out[s][b] = fc_b + sum_hg fcp; re-zeroes the mailbox for replay.
// ---------------------------------------------------------------------------
__global__ void __launch_bounds__(512) final_kernel(const float* __restrict__ fc_b,
                                                    float* __restrict__ out) {
    const int idx = blockIdx.x * 512 + threadIdx.x;
    if (idx < 2 * BG * HG * 32 * 4)                  // 32768 u64 mail words
        d_hmail[idx] = 0ull;
    if (idx >= SEQ * BATCH) return;
    const int s  = idx >> 6;
    const int b6 = idx & 63;
    const int bg = b6 >> 2;
    const int bl = b6 & 3;
    float sum = fc_b[0];
#pragma unroll
    for (int hg = 0; hg < HG; hg++)
        sum += d_fcp[((size_t)(bg * HG + hg) * SEQ + s) * 4 + bl];
    out[idx] = sum;
}

extern "C" void kernel_launch(void* const* d_in, const int* in_sizes, int n_in,
                              void* d_out, int out_size) {
    const float* x    = (const float*)d_in[0];
    const float* w_ih = (const float*)d_in[1];
    const float* w_hh = (const float*)d_in[2];
    const float* b_ih = (const float*)d_in[3];
    const float* b_hh = (const float*)d_in[4];
    const float* fc_w = (const float*)d_in[5];
    const float* fc_b = (const float*)d_in[6];
    float* out = (float*)d_out;

    dim3 ga(SEQ, G3 / 64);
    xg_kernel<<<ga, 256>>>(x, w_ih, b_ih);                 // input projections
    scan_kernel<<<NCTA, 256>>>(w_hh, b_hh, fc_w);          // ready-order scan
    final_kernel<<<(SEQ * BATCH + 511) / 512, 512>>>(fc_b, out);
}